// round 17
// baseline (speedup 1.0000x reference)
#include <cuda_runtime.h>
#include <cuda_bf16.h>
#include <cstdint>

#define HID  200
#define DD   8
#define SB   8            // samples per block
#define MM   80           // GEMM M: 8 samples * 10 rows (9 used + 1 pad)
#define PR   104          // padded k-pairs (208 k, 13 chunks of k16)
#define AST  108          // A smem row stride in u32 (bank-clean: 108%32=12)
#define RS   204          // Cb row stride (floats)
#define NTH  800          // 25 warps: warp = (mi 0..4) x (ni 0..4)
#define NWARP 25
#define EPSV 0.1f
#define DSMEM ((2 * MM * AST + MM * RS) * 4)   // Abh+Abl (u32) + Cb (f32) = 134400 B

typedef unsigned int u32;
typedef unsigned long long u64;

// bf16-split packed B planes: g_Bp[phase][(pair*HID + n)*2 + {0=hi,1=lo}]
// each u32 = bf16x2 over k-pair (2p, 2p+1). phase: 0=W1, 1=W2, 2=W2^T, 3=W1^T
__device__ __align__(16) u32 g_Bp[4][PR * HID * 2];

__global__ void prepW(const float* __restrict__ W1, const float* __restrict__ W2) {
    int idx = blockIdx.x * blockDim.x + threadIdx.x;
    if (idx >= PR * HID) return;
    int p = idx / HID, n = idx % HID;
    if (p < 100) {
        int k0 = 2 * p, k1 = 2 * p + 1;
        float wv[4][2] = {
            { W1[k0 * HID + n], W1[k1 * HID + n] },
            { W2[k0 * HID + n], W2[k1 * HID + n] },
            { W2[n * HID + k0], W2[n * HID + k1] },
            { W1[n * HID + k0], W1[n * HID + k1] } };
        #pragma unroll
        for (int ph = 0; ph < 4; ph++) {
            __nv_bfloat162 h = __floats2bfloat162_rn(wv[ph][0], wv[ph][1]);
            float r0 = wv[ph][0] - __bfloat162float(h.x);
            float r1 = wv[ph][1] - __bfloat162float(h.y);
            __nv_bfloat162 l = __floats2bfloat162_rn(r0, r1);
            g_Bp[ph][idx * 2]     = *reinterpret_cast<u32*>(&h);
            g_Bp[ph][idx * 2 + 1] = *reinterpret_cast<u32*>(&l);
        }
    } else {
        #pragma unroll
        for (int ph = 0; ph < 4; ph++) {
            g_Bp[ph][idx * 2] = 0u; g_Bp[ph][idx * 2 + 1] = 0u;
        }
    }
}

__device__ __forceinline__ float sigm(float x)     { return 1.0f / (1.0f + expf(-x)); }
__device__ __forceinline__ float softplusf(float x){ return fmaxf(x, 0.0f) + log1pf(expf(-fabsf(x))); }

__device__ __forceinline__ u32 bfpack(float a, float b) {
    __nv_bfloat162 p = __floats2bfloat162_rn(a, b);
    return *reinterpret_cast<u32*>(&p);
}
__device__ __forceinline__ float2 bfunpack(u32 v) {
    return __bfloat1622float2(*reinterpret_cast<__nv_bfloat162*>(&v));
}

// Split-store a col-pair value into the bf16 hi/lo A planes.
__device__ __forceinline__ void storeA(u32* Abh, u32* Abl, int row, int c2,
                                       float v0, float v1) {
    __nv_bfloat162 h = __floats2bfloat162_rn(v0, v1);
    float r0 = v0 - __bfloat162float(h.x);
    float r1 = v1 - __bfloat162float(h.y);
    __nv_bfloat162 l = __floats2bfloat162_rn(r0, r1);
    Abh[row * AST + c2] = *reinterpret_cast<u32*>(&h);
    Abl[row * AST + c2] = *reinterpret_cast<u32*>(&l);
}

__device__ __forceinline__ void mma16(float& c0, float& c1, float& c2, float& c3,
                                      u32 a0, u32 a1, u32 a2, u32 a3, u32 b0, u32 b1) {
    asm volatile(
        "mma.sync.aligned.m16n8k16.row.col.f32.bf16.bf16.f32 "
        "{%0,%1,%2,%3},{%4,%5,%6,%7},{%8,%9},{%0,%1,%2,%3};"
        : "+f"(c0), "+f"(c1), "+f"(c2), "+f"(c3)
        : "r"(a0), "r"(a1), "r"(a2), "r"(a3), "r"(b0), "r"(b1));
}

// One phase: Cb[80x200] = A[80x208] @ B_p[208x200], bf16 2-term split (3 products).
// warp (mi,ni) owns rows [16mi,16mi+16) x cols [40ni,40ni+40).
__device__ __forceinline__ void gemm_phase(const u32* __restrict__ Bp,
                                           const u32* Abh, const u32* Abl, float* Cb,
                                           int mi, int ni, int lane) {
    float C[5][4];
    #pragma unroll
    for (int t = 0; t < 5; t++) { C[t][0] = 0; C[t][1] = 0; C[t][2] = 0; C[t][3] = 0; }
    const int arow = mi * 16 + (lane >> 2);
    const u32* ah0p = Abh + arow * AST + (lane & 3);
    const u32* ah1p = Abh + (arow + 8) * AST + (lane & 3);
    const u32* al0p = Abl + arow * AST + (lane & 3);
    const u32* al1p = Abl + (arow + 8) * AST + (lane & 3);
    const u32* bbase = Bp + ((lane & 3) * HID + ni * 40 + (lane >> 2)) * 2;
    for (int p0 = 0; p0 < PR; p0 += 8) {
        u32 A0h = ah0p[p0], A1h = ah1p[p0], A2h = ah0p[p0 + 4], A3h = ah1p[p0 + 4];
        u32 A0l = al0p[p0], A1l = al1p[p0], A2l = al0p[p0 + 4], A3l = al1p[p0 + 4];
        #pragma unroll
        for (int t = 0; t < 5; t++) {
            u64 B0 = *reinterpret_cast<const u64*>(bbase + (p0 * HID + t * 8) * 2);
            u64 B1 = *reinterpret_cast<const u64*>(bbase + ((p0 + 4) * HID + t * 8) * 2);
            u32 b0h = (u32)B0, b0l = (u32)(B0 >> 32);
            u32 b1h = (u32)B1, b1l = (u32)(B1 >> 32);
            mma16(C[t][0], C[t][1], C[t][2], C[t][3], A0h, A1h, A2h, A3h, b0h, b1h);
            mma16(C[t][0], C[t][1], C[t][2], C[t][3], A0h, A1h, A2h, A3h, b0l, b1l);
            mma16(C[t][0], C[t][1], C[t][2], C[t][3], A0l, A1l, A2l, A3l, b0h, b1h);
        }
    }
    float* cp = Cb + (mi * 16 + (lane >> 2)) * RS + ni * 40 + (lane & 3) * 2;
    #pragma unroll
    for (int t = 0; t < 5; t++) {
        *reinterpret_cast<float2*>(cp + t * 8)          = make_float2(C[t][0], C[t][1]);
        *reinterpret_cast<float2*>(cp + t * 8 + 8 * RS) = make_float2(C[t][2], C[t][3]);
    }
}

__global__ void __launch_bounds__(NTH, 1) lnn_kernel(
    const float* __restrict__ z,
    const float* __restrict__ W0, const float* __restrict__ b0,
    const float* __restrict__ b1, const float* __restrict__ b2,
    const float* __restrict__ W3,
    float* __restrict__ out, int n)
{
    extern __shared__ u32 smu[];
    u32* Abh = smu;                     // [80][108] bf16x2 hi plane
    u32* Abl = smu + MM * AST;          // [80][108] bf16x2 lo plane
    float* Cb = reinterpret_cast<float*>(smu + 2 * MM * AST);   // [80][204] fp32
    __shared__ u32 th2b[HID][SB][4];    // bf16-packed th2 (8 dirs) per (col, sample)
    __shared__ float shz[SB][16];
    __shared__ float sh_g[SB][16];
    __shared__ float sh_H[SB][8][16];

    const int tid  = threadIdx.x;
    const int lane = tid & 31, warp = tid >> 5;
    const int mi = warp / 5, ni = warp % 5;
    const int s   = tid & 7;            // sample for epilogue unit
    const int c2  = tid >> 3;           // col pair 0..99 (cols 2c2, 2c2+1)
    const int e0  = 2 * c2, e1 = 2 * c2 + 1;
    const int base = blockIdx.x * SB;

    for (int i = tid; i < SB * 16; i += NTH) {
        int smp = base + (i >> 4);
        if (smp >= n) smp = n - 1;
        shz[i >> 4][i & 15] = z[smp * 16 + (i & 15)];
    }
    // zero the pad pairs (100..103) of every A row, both planes
    for (int i = tid; i < MM * 4; i += NTH) {
        int row = i >> 2, pc = 100 + (i & 3);
        Abh[row * AST + pc] = 0u;
        Abl[row * AST + pc] = 0u;
    }
    __syncthreads();

    float s1r[2], s2r[2];

    // ---------- phase 0: x1 = z@W0 + b0 ; seed tangents (bf16-split into A) ----------
    {
        float2 bb = *reinterpret_cast<const float2*>(&b0[e0]);
        float x0 = bb.x, x1 = bb.y;
        #pragma unroll
        for (int m = 0; m < 16; m++) {
            float2 wv = *reinterpret_cast<const float2*>(&W0[m * HID + e0]);
            float zm = shz[s][m];
            x0 = fmaf(zm, wv.x, x0);
            x1 = fmaf(zm, wv.y, x1);
        }
        s1r[0] = sigm(x0); s1r[1] = sigm(x1);
        storeA(Abh, Abl, s * 10 + 8, c2, softplusf(x0), softplusf(x1));   // h1
        Abh[(s * 10 + 9) * AST + c2] = 0u;   // pad row
        Abl[(s * 10 + 9) * AST + c2] = 0u;
        #pragma unroll
        for (int d = 0; d < DD; d++) {
            float2 wv = *reinterpret_cast<const float2*>(&W0[(DD + d) * HID + e0]);
            storeA(Abh, Abl, s * 10 + d, c2, s1r[0] * wv.x, s1r[1] * wv.y);   // th1
        }
    }
    __syncthreads();

    // ---------- phase 1: W1 -> x2 + t2 ----------
    gemm_phase(g_Bp[0], Abh, Abl, Cb, mi, ni, lane);
    __syncthreads();
    {
        float2 bb = *reinterpret_cast<const float2*>(&b1[e0]);
        float x0 = Cb[(s * 10 + 8) * RS + e0] + bb.x;
        float x1 = Cb[(s * 10 + 8) * RS + e1] + bb.y;
        float sA = sigm(x0), sB = sigm(x1);
        s2r[0] = sA; s2r[1] = sB;
        float v0[DD], v1[DD];
        #pragma unroll
        for (int d = 0; d < DD; d++) {
            v0[d] = sA * Cb[(s * 10 + d) * RS + e0];   // th2 = s2*t2
            v1[d] = sB * Cb[(s * 10 + d) * RS + e1];
            storeA(Abh, Abl, s * 10 + d, c2, v0[d], v1[d]);
        }
        storeA(Abh, Abl, s * 10 + 8, c2, softplusf(x0), softplusf(x1));   // h2
        th2b[e0][s][0] = bfpack(v0[0], v0[1]); th2b[e0][s][1] = bfpack(v0[2], v0[3]);
        th2b[e0][s][2] = bfpack(v0[4], v0[5]); th2b[e0][s][3] = bfpack(v0[6], v0[7]);
        th2b[e1][s][0] = bfpack(v1[0], v1[1]); th2b[e1][s][1] = bfpack(v1[2], v1[3]);
        th2b[e1][s][2] = bfpack(v1[4], v1[5]); th2b[e1][s][3] = bfpack(v1[6], v1[7]);
    }
    __syncthreads();

    // ---------- phase 2: W2 -> x3 + t3 ----------
    gemm_phase(g_Bp[1], Abh, Abl, Cb, mi, ni, lane);
    __syncthreads();
    {
        float2 bb = *reinterpret_cast<const float2*>(&b2[e0]);
        float2 w3 = *reinterpret_cast<const float2*>(&W3[e0]);
        float x0 = Cb[(s * 10 + 8) * RS + e0] + bb.x;
        float x1 = Cb[(s * 10 + 8) * RS + e1] + bb.y;
        float sA = sigm(x0), sB = sigm(x1);
        float cA = w3.x * sA * (1.0f - sA);
        float cB = w3.y * sB * (1.0f - sB);
        #pragma unroll
        for (int d = 0; d < DD; d++)
            storeA(Abh, Abl, s * 10 + d, c2,
                   cA * Cb[(s * 10 + d) * RS + e0],
                   cB * Cb[(s * 10 + d) * RS + e1]);                     // delta-d3
        storeA(Abh, Abl, s * 10 + 8, c2, w3.x * sA, w3.y * sB);          // d3
    }
    __syncthreads();

    // ---------- phase 3: W2^T -> u2 + r2 ----------
    gemm_phase(g_Bp[2], Abh, Abl, Cb, mi, ni, lane);
    __syncthreads();
    {
        float u20 = Cb[(s * 10 + 8) * RS + e0];
        float u21 = Cb[(s * 10 + 8) * RS + e1];
        float sA = s2r[0], sB = s2r[1];
        float kA = (1.0f - sA) * u20, kB = (1.0f - sB) * u21;
        float tA[DD], tB[DD];
        { float2 p;
          p = bfunpack(th2b[e0][s][0]); tA[0] = p.x; tA[1] = p.y;
          p = bfunpack(th2b[e0][s][1]); tA[2] = p.x; tA[3] = p.y;
          p = bfunpack(th2b[e0][s][2]); tA[4] = p.x; tA[5] = p.y;
          p = bfunpack(th2b[e0][s][3]); tA[6] = p.x; tA[7] = p.y;
          p = bfunpack(th2b[e1][s][0]); tB[0] = p.x; tB[1] = p.y;
          p = bfunpack(th2b[e1][s][1]); tB[2] = p.x; tB[3] = p.y;
          p = bfunpack(th2b[e1][s][2]); tB[4] = p.x; tB[5] = p.y;
          p = bfunpack(th2b[e1][s][3]); tB[6] = p.x; tB[7] = p.y; }
        #pragma unroll
        for (int d = 0; d < DD; d++)
            storeA(Abh, Abl, s * 10 + d, c2,
                   fmaf(sA, Cb[(s * 10 + d) * RS + e0], kA * tA[d]),
                   fmaf(sB, Cb[(s * 10 + d) * RS + e1], kB * tB[d]));    // delta-d2
        storeA(Abh, Abl, s * 10 + 8, c2, sA * u20, sB * u21);            // d2
    }
    __syncthreads();

    // ---------- phase 4: W1^T -> u1 + r1 (results to Cb fp32 for final dots) ----------
    gemm_phase(g_Bp[3], Abh, Abl, Cb, mi, ni, lane);
    __syncthreads();
    {
        float u10 = Cb[(s * 10 + 8) * RS + e0];
        float u11 = Cb[(s * 10 + 8) * RS + e1];
        float sA = s1r[0], sB = s1r[1];
        float coA = sA * (1.0f - sA) * u10;
        float coB = sB * (1.0f - sB) * u11;
        #pragma unroll
        for (int d = 0; d < DD; d++) {
            float2 wv = *reinterpret_cast<const float2*>(&W0[(DD + d) * HID + e0]);
            Cb[(s * 10 + d) * RS + e0] = fmaf(sA, Cb[(s * 10 + d) * RS + e0], coA * wv.x);
            Cb[(s * 10 + d) * RS + e1] = fmaf(sB, Cb[(s * 10 + d) * RS + e1], coB * wv.y);   // delta-d1
        }
        Cb[(s * 10 + 8) * RS + e0] = sA * u10;   // d1
        Cb[(s * 10 + 8) * RS + e1] = sB * u11;
    }
    __syncthreads();

    // ---------- final dots (read Cb fp32) ----------
    for (int idx = warp; idx < SB * 16; idx += NWARP) {
        int ss = idx >> 4, m = idx & 15;
        float a = 0.0f;
        for (int k = lane; k < HID; k += 32)
            a = fmaf(W0[m * HID + k], Cb[(ss * 10 + 8) * RS + k], a);
        #pragma unroll
        for (int off = 16; off > 0; off >>= 1) a += __shfl_xor_sync(0xffffffffu, a, off);
        if (lane == 0) sh_g[ss][m] = a;
    }
    for (int idx = warp; idx < SB * 128; idx += NWARP) {
        int ss = idx >> 7;
        int r = idx & 127;
        int d = r >> 4, m = r & 15;
        float a = 0.0f;
        for (int k = lane; k < HID; k += 32)
            a = fmaf(W0[m * HID + k], Cb[(ss * 10 + d) * RS + k], a);
        #pragma unroll
        for (int off = 16; off > 0; off >>= 1) a += __shfl_xor_sync(0xffffffffu, a, off);
        if (lane == 0) sh_H[ss][d][m] = a;
    }
    __syncthreads();

    // ---------- per-sample 8x8 solve + output ----------
    if (tid < SB && base + tid < n) {
        const int ss = tid;
        float Mt[DD][DD], Fv[DD], av2[DD], vv[DD];
        #pragma unroll
        for (int c = 0; c < DD; c++) vv[c] = shz[ss][DD + c];
        for (int r = 0; r < DD; r++)
            for (int c = 0; c < DD; c++)
                Mt[r][c] = sh_H[ss][r][DD + c] + ((r == c) ? 2.0f * EPSV : 0.0f);
        for (int p = 0; p < DD; p++) {
            float f = sh_g[ss][p];
            for (int c = 0; c < DD; c++) f -= sh_H[ss][p][c] * vv[c];
            Fv[p] = f;
        }
        for (int col = 0; col < DD; col++) {
            int piv = col; float best = fabsf(Mt[col][col]);
            for (int r = col + 1; r < DD; r++) {
                float m = fabsf(Mt[r][col]);
                if (m > best) { best = m; piv = r; }
            }
            if (piv != col) {
                for (int c = col; c < DD; c++) { float t = Mt[col][c]; Mt[col][c] = Mt[piv][c]; Mt[piv][c] = t; }
                float t = Fv[col]; Fv[col] = Fv[piv]; Fv[piv] = t;
            }
            float inv = 1.0f / Mt[col][col];
            for (int r = col + 1; r < DD; r++) {
                float fac = Mt[r][col] * inv;
                for (int c = col; c < DD; c++) Mt[r][c] -= fac * Mt[col][c];
                Fv[r] -= fac * Fv[col];
            }
        }
        for (int r = DD - 1; r >= 0; r--) {
            float x = Fv[r];
            for (int c = r + 1; c < DD; c++) x -= Mt[r][c] * av2[c];
            av2[r] = x / Mt[r][r];
        }
        const int gi = (base + ss) * 16;
        #pragma unroll
        for (int jj = 0; jj < DD; jj++) out[gi + jj] = vv[jj];
        #pragma unroll
        for (int jj = 0; jj < DD; jj++) out[gi + DD + jj] = av2[jj];
    }
}

extern "C" void kernel_launch(void* const* d_in, const int* in_sizes, int n_in,
                              void* d_out, int out_size) {
    const float* z  = (const float*)d_in[1];
    const float* W0 = (const float*)d_in[2];
    const float* b0 = (const float*)d_in[3];
    const float* W1 = (const float*)d_in[4];
    const float* b1 = (const float*)d_in[5];
    const float* W2 = (const float*)d_in[6];
    const float* b2 = (const float*)d_in[7];
    const float* W3 = (const float*)d_in[8];
    float* out = (float*)d_out;

    const int n = in_sizes[1] / 16;

    cudaFuncSetAttribute(lnn_kernel, cudaFuncAttributeMaxDynamicSharedMemorySize, DSMEM);

    prepW<<<(PR * HID + 255) / 256, 256>>>(W1, W2);

    const int blocks = (n + SB - 1) / SB;
    lnn_kernel<<<blocks, NTH, DSMEM>>>(z, W0, b0, b1, b2, W3, out, n);
}